// round 11
// baseline (speedup 1.0000x reference)
#include <cuda_runtime.h>
#include <cstddef>
#include <cstdint>

#define NN 100000
#define DD 128
#define SCAN_T 1024
#define CHUNK ((NN + SCAN_T - 1) / SCAN_T)   // 98

__device__ float g_agg[(size_t)NN * DD];     // mean-aggregated neighbor feats
__device__ float g_q0 [NN], g_q1 [NN];       // x1·u0, x1·u1
__device__ float g_xv0[NN], g_xv1[NN];       // x1·v0, x1·v1
__device__ float g_r0 [NN], g_r1 [NN];
__device__ float g_inv[NN];
__device__ int   g_cnt[NN];                  // counts, then reused as cursors
__device__ int   g_off[NN + 1];
__device__ int   g_csrc[600000 + 1024];      // CSR src lists (E max 600k)
__device__ float g_u0[DD], g_u1[DD], g_v0[DD], g_v1[DD];
__device__ float g_c;

typedef unsigned long long ull;

// ---------------------------------------------------------------------------
__global__ void count_kernel(const int* __restrict__ dst, int e) {
    int i = blockIdx.x * blockDim.x + threadIdx.x;
    if (i < e) atomicAdd(&g_cnt[dst[i]], 1);
}

// Single-block exclusive scan of g_cnt -> g_off, plus inv-degree.
__global__ void scan_kernel(int n) {
    __shared__ int sh[SCAN_T];
    int t = threadIdx.x;
    int lo = t * CHUNK, hi = min(lo + CHUNK, n);
    int s = 0;
    for (int i = lo; i < hi; i++) s += g_cnt[i];
    sh[t] = s;
    __syncthreads();
    for (int o = 1; o < SCAN_T; o <<= 1) {
        int v = (t >= o) ? sh[t - o] : 0;
        __syncthreads();
        sh[t] += v;
        __syncthreads();
    }
    int run = (t > 0) ? sh[t - 1] : 0;
    for (int i = lo; i < hi; i++) {
        int c = g_cnt[i];
        g_off[i] = run;
        run += c;
        g_inv[i] = 1.0f / fmaxf((float)c, 1.0f);
    }
    if (hi == n) g_off[n] = run;
}

// Fill CSR: g_cnt is zeroed cursors at this point.
__global__ void fill_kernel(const int* __restrict__ src,
                            const int* __restrict__ dst, int e) {
    int i = blockIdx.x * blockDim.x + threadIdx.x;
    if (i >= e) return;
    int d = __ldg(dst + i);
    int pos = atomicAdd(&g_cnt[d], 1);
    g_csrc[g_off[d] + pos] = __ldg(src + i);
}

// ---------------------------------------------------------------------------
// CSR gather: one warp per node, sum in-neighbor rows, scale by inv, store.
// No atomics, no accumulator memset.
// ---------------------------------------------------------------------------
__global__ void gather_kernel(const float* __restrict__ x, int n) {
    int v    = (blockIdx.x * blockDim.x + threadIdx.x) >> 5;
    int lane = threadIdx.x & 31;
    if (v >= n) return;
    int b = __ldg(&g_off[v]);
    int e = __ldg(&g_off[v + 1]);
    float4 acc = make_float4(0.f, 0.f, 0.f, 0.f);
    for (int i = b; i < e; i++) {
        int s = __ldg(&g_csrc[i]);
        float4 t = *(const float4*)(x + (size_t)s * DD + lane * 4);
        acc.x += t.x; acc.y += t.y; acc.z += t.z; acc.w += t.w;
    }
    float inv = g_inv[v];
    acc.x *= inv; acc.y *= inv; acc.z *= inv; acc.w *= inv;
    *(float4*)(g_agg + (size_t)v * DD + lane * 4) = acc;
}

// ---------------------------------------------------------------------------
// u/v projections: u0=W2l@w0, u1=W2l@w1, v0=W2r@w0, v1=W2r@w1; c=b2·(w0+w1)+blin
// ---------------------------------------------------------------------------
__global__ void uv_kernel(const float* __restrict__ W2l,
                          const float* __restrict__ W2r,
                          const float* __restrict__ b2,
                          const float* __restrict__ Wlin,
                          const float* __restrict__ blin) {
    __shared__ float w0s[DD], w1s[DD];
    int i = threadIdx.x;
    w0s[i] = Wlin[i];
    w1s[i] = Wlin[DD + i];
    __syncthreads();
    float u0 = 0.f, u1 = 0.f, v0 = 0.f, v1 = 0.f;
    const float* rl = W2l + (size_t)i * DD;
    const float* rr = W2r + (size_t)i * DD;
    #pragma unroll 4
    for (int j = 0; j < DD; j++) {
        float a = rl[j], b = rr[j];
        u0 = fmaf(a, w0s[j], u0);
        u1 = fmaf(a, w1s[j], u1);
        v0 = fmaf(b, w0s[j], v0);
        v1 = fmaf(b, w1s[j], v1);
    }
    g_u0[i] = u0; g_u1[i] = u1; g_v0[i] = v0; g_v1[i] = v1;
    if (i == 0) {
        float c = blin[0];
        for (int j = 0; j < DD; j++)
            c = fmaf(b2[j], w0s[j] + w1s[j], c);
        g_c = c;
    }
}

// ---------------------------------------------------------------------------
// Layer-1 packed dual-GEMM fused with projection epilogue (x1 never stored):
//   x1row = relu( agg @ W1l + b1 + emb @ W1r )      (agg pre-scaled by inv)
//   q0..xv1 = x1row · {u0,u1,v0,v1}
// ---------------------------------------------------------------------------
#define TILE_ROWS 64
#define GEMM_THREADS 512
#define GEMM_SMEM_FLOATS (32768 + 16384 + 128)
#define GEMM_SMEM_BYTES  (GEMM_SMEM_FLOATS * 4)

__device__ __forceinline__ void ffma2(ull& d, ull a, ull b) {
    asm volatile("fma.rn.f32x2 %0, %1, %2, %0;" : "+l"(d) : "l"(a), "l"(b));
}

__global__ __launch_bounds__(GEMM_THREADS, 1)
void sage_gemm_fused(const float* __restrict__ agg,
                     const float* __restrict__ xin,
                     const float* __restrict__ Wl,
                     const float* __restrict__ bias,
                     const float* __restrict__ Wr,
                     int n) {
    extern __shared__ float sm[];
    float* Wi  = sm;                       // [128][128] float2 pairs (wl,wr)
    float* AXs = Wi + 32768;               // [64][128] float2 pairs (a,x)
    float* bs  = AXs + TILE_ROWS * DD * 2; // [128]

    const int tid = threadIdx.x;

    for (int i = tid; i < 4096; i += GEMM_THREADS) {
        float4 l = ((const float4*)Wl)[i];
        float4 r = ((const float4*)Wr)[i];
        ((float4*)Wi)[i * 2 + 0] = make_float4(l.x, r.x, l.y, r.y);
        ((float4*)Wi)[i * 2 + 1] = make_float4(l.z, r.z, l.w, r.w);
    }
    if (tid < DD) bs[tid] = bias[tid];

    const int lane = tid & 31;
    const int rg   = tid >> 5;
    const int r0   = rg * 4;

    float u0r[4], u1r[4], v0r[4], v1r[4];
    #pragma unroll
    for (int j = 0; j < 4; j++) {
        int c = lane + 32 * j;
        u0r[j] = g_u0[c]; u1r[j] = g_u1[c];
        v0r[j] = g_v0[c]; v1r[j] = g_v1[c];
    }
    __syncthreads();

    const int ntiles = (n + TILE_ROWS - 1) / TILE_ROWS;
    for (int t = blockIdx.x; t < ntiles; t += gridDim.x) {
        const int base = t * TILE_ROWS;

        for (int i = tid; i < TILE_ROWS * 32; i += GEMM_THREADS) {
            int row = i >> 5, c4 = i & 31;
            int gr = base + row;
            if (gr < n) {
                float4 a = ((const float4*)(agg + (size_t)gr * DD))[c4];
                float4 x = ((const float4*)(xin + (size_t)gr * DD))[c4];
                float4* dst4 = (float4*)(AXs + (row * DD + c4 * 4) * 2);
                dst4[0] = make_float4(a.x, x.x, a.y, x.y);
                dst4[1] = make_float4(a.z, x.z, a.w, x.w);
            }
        }
        __syncthreads();

        ull acc[4][4];
        #pragma unroll
        for (int r = 0; r < 4; r++)
            #pragma unroll
            for (int j = 0; j < 4; j++) acc[r][j] = 0ull;

        const ull* Wiu = (const ull*)Wi;
        const ull* AXu = (const ull*)AXs;

        #pragma unroll 4
        for (int k = 0; k < DD; k += 2) {
            ull w0[4], w1[4];
            #pragma unroll
            for (int j = 0; j < 4; j++) {
                w0[j] = Wiu[(k    ) * DD + lane + 32 * j];
                w1[j] = Wiu[(k + 1) * DD + lane + 32 * j];
            }
            #pragma unroll
            for (int r = 0; r < 4; r++) {
                ulonglong2 ax = *(const ulonglong2*)(AXu + (r0 + r) * DD + k);
                #pragma unroll
                for (int j = 0; j < 4; j++) {
                    ffma2(acc[r][j], ax.x, w0[j]);
                    ffma2(acc[r][j], ax.y, w1[j]);
                }
            }
        }

        #pragma unroll
        for (int r = 0; r < 4; r++) {
            int gr = base + r0 + r;
            float p0 = 0.f, p1 = 0.f, p2 = 0.f, p3 = 0.f;
            #pragma unroll
            for (int j = 0; j < 4; j++) {
                int c = lane + 32 * j;
                float2 v = *(float2*)&acc[r][j];
                float s = fmaxf(v.x + v.y + bs[c], 0.f);
                p0 = fmaf(s, u0r[j], p0);
                p1 = fmaf(s, u1r[j], p1);
                p2 = fmaf(s, v0r[j], p2);
                p3 = fmaf(s, v1r[j], p3);
            }
            #pragma unroll
            for (int o = 16; o > 0; o >>= 1) {
                p0 += __shfl_down_sync(0xFFFFFFFFu, p0, o);
                p1 += __shfl_down_sync(0xFFFFFFFFu, p1, o);
                p2 += __shfl_down_sync(0xFFFFFFFFu, p2, o);
                p3 += __shfl_down_sync(0xFFFFFFFFu, p3, o);
            }
            if (lane == 0 && gr < n) {
                g_q0 [gr] = p0;
                g_q1 [gr] = p1;
                g_xv0[gr] = p2;
                g_xv1[gr] = p3;
            }
        }
        __syncthreads();
    }
}

// ---------------------------------------------------------------------------
// Fold with CSR (replaces scatter2 + fold):
//   r0[v] = inv[v] * Σ_{e:dst=v} q0[src_e] + xv0[v]   (r1 likewise)
// ---------------------------------------------------------------------------
__global__ void fold_kernel(int n) {
    int v = blockIdx.x * blockDim.x + threadIdx.x;
    if (v >= n) return;
    int b = __ldg(&g_off[v]);
    int e = __ldg(&g_off[v + 1]);
    float s0 = 0.f, s1 = 0.f;
    for (int i = b; i < e; i++) {
        int s = __ldg(&g_csrc[i]);
        s0 += g_q0[s];
        s1 += g_q1[s];
    }
    float inv = g_inv[v];
    g_r0[v] = fmaf(inv, s0, g_xv0[v]);
    g_r1[v] = fmaf(inv, s1, g_xv1[v]);
}

// ---------------------------------------------------------------------------
__global__ void predict_kernel(const int* __restrict__ s,
                               const int* __restrict__ d,
                               float* __restrict__ out, int L) {
    int l = blockIdx.x * blockDim.x + threadIdx.x;
    if (l >= L) return;
    out[l] = g_r0[__ldg(s + l)] + g_r1[__ldg(d + l)] + g_c;
}

// ---------------------------------------------------------------------------
extern "C" void kernel_launch(void* const* d_in, const int* in_sizes, int n_in,
                              void* d_out, int out_size) {
    const int*   ei   = (const int*)d_in[0];
    const int*   eli  = (const int*)d_in[1];
    const float* emb  = (const float*)d_in[2];
    const float* W1l  = (const float*)d_in[3];
    const float* b1   = (const float*)d_in[4];
    const float* W1r  = (const float*)d_in[5];
    const float* W2l  = (const float*)d_in[6];
    const float* b2   = (const float*)d_in[7];
    const float* W2r  = (const float*)d_in[8];
    const float* Wlin = (const float*)d_in[9];
    const float* blin = (const float*)d_in[10];
    float*       out  = (float*)d_out;

    const int E = in_sizes[0] / 2;
    const int L = in_sizes[1] / 2;
    const int N = in_sizes[2] / DD;

    const int* src = ei;
    const int* dst = ei + E;
    const int* ls  = eli;
    const int* ld  = eli + L;

    void* p_cnt = nullptr; cudaGetSymbolAddress(&p_cnt, g_cnt);
    float* agg = nullptr; cudaGetSymbolAddress((void**)&agg, g_agg);

    cudaFuncSetAttribute(sage_gemm_fused,
                         cudaFuncAttributeMaxDynamicSharedMemorySize,
                         GEMM_SMEM_BYTES);

    // CSR build: count -> scan -> fill (cnt reused as cursors)
    cudaMemsetAsync(p_cnt, 0, sizeof(int) * (size_t)N);
    count_kernel<<<(E + 255) / 256, 256>>>(dst, E);
    scan_kernel<<<1, SCAN_T>>>(N);
    cudaMemsetAsync(p_cnt, 0, sizeof(int) * (size_t)N);
    fill_kernel<<<(E + 255) / 256, 256>>>(src, dst, E);

    uv_kernel<<<1, DD>>>(W2l, W2r, b2, Wlin, blin);

    // Layer 1: CSR gather (mean agg, pre-scaled) + fused GEMM/projection
    gather_kernel<<<((size_t)N * 32 + 255) / 256, 256>>>(emb, N);
    sage_gemm_fused<<<148, GEMM_THREADS, GEMM_SMEM_BYTES>>>(
        agg, emb, W1l, b1, W1r, N);

    // Layer 2: CSR fold + predict
    fold_kernel<<<(N + 255) / 256, 256>>>(N);
    predict_kernel<<<(L + 255) / 256, 256>>>(ls, ld, out, L);
}

// round 12
// speedup vs baseline: 1.5182x; 1.5182x over previous
#include <cuda_runtime.h>
#include <cstddef>
#include <cstdint>

#define NN 100000
#define DD 128

__device__ float g_agg[(size_t)NN * DD];   // layer-1 neighbor sums
__device__ float g_q0 [NN], g_q1 [NN];     // x1·u0, x1·u1
__device__ float g_xv0[NN], g_xv1[NN];     // x1·v0, x1·v1
__device__ float g_aq0[NN], g_aq1[NN];     // scattered q sums
__device__ float g_r0 [NN], g_r1 [NN];
__device__ float g_inv[NN];
__device__ int   g_cnt[NN];
__device__ float g_u0[DD], g_u1[DD], g_v0[DD], g_v1[DD];
__device__ float g_c;

typedef unsigned long long ull;

// ---------------------------------------------------------------------------
__global__ void deg_kernel(const int* __restrict__ dst, int e) {
    int i = blockIdx.x * blockDim.x + threadIdx.x;
    if (i < e) atomicAdd(&g_cnt[dst[i]], 1);
}

// inv-degree + zero the scalar accumulators (replaces two memsets)
__global__ void inv_kernel(int n) {
    int i = blockIdx.x * blockDim.x + threadIdx.x;
    if (i < n) {
        g_inv[i] = 1.0f / fmaxf((float)g_cnt[i], 1.0f);
        g_aq0[i] = 0.f;
        g_aq1[i] = 0.f;
    }
}

// ---------------------------------------------------------------------------
__global__ void scatter_kernel(const float* __restrict__ x,
                               const int* __restrict__ src,
                               const int* __restrict__ dst, int e) {
    int w    = (blockIdx.x * blockDim.x + threadIdx.x) >> 5;
    int lane = threadIdx.x & 31;
    if (w >= e) return;
    int s = __ldg(src + w);
    int d = __ldg(dst + w);
    float4 v = *(const float4*)(x + (size_t)s * DD + lane * 4);
    atomicAdd((float4*)(g_agg + (size_t)d * DD + lane * 4), v);
}

// ---------------------------------------------------------------------------
// Scalar scatter for layer 2: aq0[d] += q0[s], aq1[d] += q1[s]
// ---------------------------------------------------------------------------
__global__ void scatter2_kernel(const int* __restrict__ src,
                                const int* __restrict__ dst, int e) {
    int i = blockIdx.x * blockDim.x + threadIdx.x;
    if (i >= e) return;
    int s = __ldg(src + i);
    int d = __ldg(dst + i);
    atomicAdd(&g_aq0[d], g_q0[s]);
    atomicAdd(&g_aq1[d], g_q1[s]);
}

// ---------------------------------------------------------------------------
// u/v projections, parallel: one warp per output row.
//   u0 = W2l @ w0, u1 = W2l @ w1, v0 = W2r @ w0, v1 = W2r @ w1
//   c  = b2·(w0+w1) + blin
// 16 blocks x 256 threads = 128 warps.
// ---------------------------------------------------------------------------
__global__ void uv_kernel(const float* __restrict__ W2l,
                          const float* __restrict__ W2r,
                          const float* __restrict__ b2,
                          const float* __restrict__ Wlin,
                          const float* __restrict__ blin) {
    int w    = (blockIdx.x * blockDim.x + threadIdx.x) >> 5;  // row 0..127
    int lane = threadIdx.x & 31;
    if (w >= DD) return;
    const float* rl = W2l + (size_t)w * DD;
    const float* rr = W2r + (size_t)w * DD;
    float u0 = 0.f, u1 = 0.f, v0 = 0.f, v1 = 0.f;
    #pragma unroll
    for (int jj = 0; jj < 4; jj++) {
        int j = lane + 32 * jj;
        float a  = __ldg(rl + j);
        float b  = __ldg(rr + j);
        float w0 = __ldg(Wlin + j);
        float w1 = __ldg(Wlin + DD + j);
        u0 = fmaf(a, w0, u0);
        u1 = fmaf(a, w1, u1);
        v0 = fmaf(b, w0, v0);
        v1 = fmaf(b, w1, v1);
    }
    #pragma unroll
    for (int o = 16; o > 0; o >>= 1) {
        u0 += __shfl_down_sync(0xFFFFFFFFu, u0, o);
        u1 += __shfl_down_sync(0xFFFFFFFFu, u1, o);
        v0 += __shfl_down_sync(0xFFFFFFFFu, v0, o);
        v1 += __shfl_down_sync(0xFFFFFFFFu, v1, o);
    }
    if (lane == 0) {
        g_u0[w] = u0; g_u1[w] = u1; g_v0[w] = v0; g_v1[w] = v1;
    }
    // constant c: one warp computes it
    if (w == 0) {
        float c = 0.f;
        #pragma unroll
        for (int jj = 0; jj < 4; jj++) {
            int j = lane + 32 * jj;
            c = fmaf(__ldg(b2 + j), __ldg(Wlin + j) + __ldg(Wlin + DD + j), c);
        }
        #pragma unroll
        for (int o = 16; o > 0; o >>= 1)
            c += __shfl_down_sync(0xFFFFFFFFu, c, o);
        if (lane == 0) g_c = c + __ldg(blin);
    }
}

// ---------------------------------------------------------------------------
// Layer-1 packed dual-GEMM fused with projection epilogue:
//   x1row = relu( (agg*inv) @ W1l + b1 + emb @ W1r )     (registers only)
//   q0 = x1row·u0, q1 = x1row·u1, xv0 = x1row·v0, xv1 = x1row·v1
// ---------------------------------------------------------------------------
#define TILE_ROWS 64
#define GEMM_THREADS 512
#define GEMM_SMEM_FLOATS (32768 + 16384 + 128)
#define GEMM_SMEM_BYTES  (GEMM_SMEM_FLOATS * 4)

__device__ __forceinline__ void ffma2(ull& d, ull a, ull b) {
    asm volatile("fma.rn.f32x2 %0, %1, %2, %0;" : "+l"(d) : "l"(a), "l"(b));
}

__global__ __launch_bounds__(GEMM_THREADS, 1)
void sage_gemm_fused(const float* __restrict__ agg,
                     const float* __restrict__ xin,
                     const float* __restrict__ Wl,
                     const float* __restrict__ bias,
                     const float* __restrict__ Wr,
                     int n) {
    extern __shared__ float sm[];
    float* Wi  = sm;                       // [128][128] float2 pairs (wl,wr)
    float* AXs = Wi + 32768;               // [64][128] float2 pairs (a,x)
    float* bs  = AXs + TILE_ROWS * DD * 2; // [128]

    const int tid = threadIdx.x;

    for (int i = tid; i < 4096; i += GEMM_THREADS) {
        float4 l = ((const float4*)Wl)[i];
        float4 r = ((const float4*)Wr)[i];
        ((float4*)Wi)[i * 2 + 0] = make_float4(l.x, r.x, l.y, r.y);
        ((float4*)Wi)[i * 2 + 1] = make_float4(l.z, r.z, l.w, r.w);
    }
    if (tid < DD) bs[tid] = bias[tid];

    const int lane = tid & 31;
    const int rg   = tid >> 5;
    const int r0   = rg * 4;

    float u0r[4], u1r[4], v0r[4], v1r[4];
    #pragma unroll
    for (int j = 0; j < 4; j++) {
        int c = lane + 32 * j;
        u0r[j] = g_u0[c]; u1r[j] = g_u1[c];
        v0r[j] = g_v0[c]; v1r[j] = g_v1[c];
    }
    __syncthreads();

    const int ntiles = (n + TILE_ROWS - 1) / TILE_ROWS;
    for (int t = blockIdx.x; t < ntiles; t += gridDim.x) {
        const int base = t * TILE_ROWS;

        for (int i = tid; i < TILE_ROWS * 32; i += GEMM_THREADS) {
            int row = i >> 5, c4 = i & 31;
            int gr = base + row;
            if (gr < n) {
                float inv = g_inv[gr];
                float4 a = ((const float4*)(agg + (size_t)gr * DD))[c4];
                float4 x = ((const float4*)(xin + (size_t)gr * DD))[c4];
                a.x *= inv; a.y *= inv; a.z *= inv; a.w *= inv;
                float4* dst4 = (float4*)(AXs + (row * DD + c4 * 4) * 2);
                dst4[0] = make_float4(a.x, x.x, a.y, x.y);
                dst4[1] = make_float4(a.z, x.z, a.w, x.w);
            }
        }
        __syncthreads();

        ull acc[4][4];
        #pragma unroll
        for (int r = 0; r < 4; r++)
            #pragma unroll
            for (int j = 0; j < 4; j++) acc[r][j] = 0ull;

        const ull* Wiu = (const ull*)Wi;
        const ull* AXu = (const ull*)AXs;

        #pragma unroll 4
        for (int k = 0; k < DD; k += 2) {
            ull w0[4], w1[4];
            #pragma unroll
            for (int j = 0; j < 4; j++) {
                w0[j] = Wiu[(k    ) * DD + lane + 32 * j];
                w1[j] = Wiu[(k + 1) * DD + lane + 32 * j];
            }
            #pragma unroll
            for (int r = 0; r < 4; r++) {
                ulonglong2 ax = *(const ulonglong2*)(AXu + (r0 + r) * DD + k);
                #pragma unroll
                for (int j = 0; j < 4; j++) {
                    ffma2(acc[r][j], ax.x, w0[j]);
                    ffma2(acc[r][j], ax.y, w1[j]);
                }
            }
        }

        #pragma unroll
        for (int r = 0; r < 4; r++) {
            int gr = base + r0 + r;
            float p0 = 0.f, p1 = 0.f, p2 = 0.f, p3 = 0.f;
            #pragma unroll
            for (int j = 0; j < 4; j++) {
                int c = lane + 32 * j;
                float2 v = *(float2*)&acc[r][j];
                float s = fmaxf(v.x + v.y + bs[c], 0.f);
                p0 = fmaf(s, u0r[j], p0);
                p1 = fmaf(s, u1r[j], p1);
                p2 = fmaf(s, v0r[j], p2);
                p3 = fmaf(s, v1r[j], p3);
            }
            #pragma unroll
            for (int o = 16; o > 0; o >>= 1) {
                p0 += __shfl_down_sync(0xFFFFFFFFu, p0, o);
                p1 += __shfl_down_sync(0xFFFFFFFFu, p1, o);
                p2 += __shfl_down_sync(0xFFFFFFFFu, p2, o);
                p3 += __shfl_down_sync(0xFFFFFFFFu, p3, o);
            }
            if (lane == 0 && gr < n) {
                g_q0 [gr] = p0;
                g_q1 [gr] = p1;
                g_xv0[gr] = p2;
                g_xv1[gr] = p3;
            }
        }
        __syncthreads();
    }
}

// ---------------------------------------------------------------------------
__global__ void fold_kernel(int n) {
    int v = blockIdx.x * blockDim.x + threadIdx.x;
    if (v >= n) return;
    float inv = g_inv[v];
    g_r0[v] = fmaf(inv, g_aq0[v], g_xv0[v]);
    g_r1[v] = fmaf(inv, g_aq1[v], g_xv1[v]);
}

// ---------------------------------------------------------------------------
__global__ void predict_kernel(const int* __restrict__ s,
                               const int* __restrict__ d,
                               float* __restrict__ out, int L) {
    int l = blockIdx.x * blockDim.x + threadIdx.x;
    if (l >= L) return;
    out[l] = g_r0[__ldg(s + l)] + g_r1[__ldg(d + l)] + g_c;
}

// ---------------------------------------------------------------------------
extern "C" void kernel_launch(void* const* d_in, const int* in_sizes, int n_in,
                              void* d_out, int out_size) {
    const int*   ei   = (const int*)d_in[0];
    const int*   eli  = (const int*)d_in[1];
    const float* emb  = (const float*)d_in[2];
    const float* W1l  = (const float*)d_in[3];
    const float* b1   = (const float*)d_in[4];
    const float* W1r  = (const float*)d_in[5];
    const float* W2l  = (const float*)d_in[6];
    const float* b2   = (const float*)d_in[7];
    const float* W2r  = (const float*)d_in[8];
    const float* Wlin = (const float*)d_in[9];
    const float* blin = (const float*)d_in[10];
    float*       out  = (float*)d_out;

    const int E = in_sizes[0] / 2;
    const int L = in_sizes[1] / 2;
    const int N = in_sizes[2] / DD;

    const int* src = ei;
    const int* dst = ei + E;
    const int* ls  = eli;
    const int* ld  = eli + L;

    void* p_agg = nullptr; cudaGetSymbolAddress(&p_agg, g_agg);
    void* p_cnt = nullptr; cudaGetSymbolAddress(&p_cnt, g_cnt);
    float* agg = (float*)p_agg;

    cudaFuncSetAttribute(sage_gemm_fused,
                         cudaFuncAttributeMaxDynamicSharedMemorySize,
                         GEMM_SMEM_BYTES);

    const int scatter_blocks = ((size_t)E * 32 + 255) / 256;

    // Setup
    cudaMemsetAsync(p_cnt, 0, sizeof(int) * (size_t)N);
    cudaMemsetAsync(p_agg, 0, sizeof(float) * (size_t)N * DD);
    deg_kernel<<<(E + 255) / 256, 256>>>(dst, E);
    inv_kernel<<<(N + 255) / 256, 256>>>(N);
    uv_kernel<<<16, 256>>>(W2l, W2r, b2, Wlin, blin);

    // Layer 1 aggregation + fused GEMM/projection (x1 never materialized)
    scatter_kernel<<<scatter_blocks, 256>>>(emb, src, dst, E);
    sage_gemm_fused<<<148, GEMM_THREADS, GEMM_SMEM_BYTES>>>(
        agg, emb, W1l, b1, W1r, N);

    // Layer 2 collapses to scalar scatter + fold
    scatter2_kernel<<<(E + 255) / 256, 256>>>(src, dst, E);
    fold_kernel<<<(N + 255) / 256, 256>>>(N);
    predict_kernel<<<(L + 255) / 256, 256>>>(ls, ld, out, L);
}

// round 13
// speedup vs baseline: 2.3640x; 1.5571x over previous
#include <cuda_runtime.h>
#include <cstddef>
#include <cstdint>

#define NN 100000
#define DD 128

__device__ float g_agg[(size_t)NN * DD];   // layer-1 neighbor sums
__device__ float g_q0 [NN], g_q1 [NN];     // x1·u0, x1·u1
__device__ float g_xv0[NN], g_xv1[NN];     // x1·v0, x1·v1
__device__ float g_aq0[NN], g_aq1[NN];     // scattered q sums
__device__ float g_r0 [NN], g_r1 [NN];
__device__ float g_inv[NN];
__device__ int   g_cnt[NN];
__device__ float g_u0[DD], g_u1[DD], g_v0[DD], g_v1[DD];
__device__ float g_c;

// ---------------------------------------------------------------------------
__global__ void deg_kernel(const int* __restrict__ dst, int e) {
    int i = blockIdx.x * blockDim.x + threadIdx.x;
    if (i < e) atomicAdd(&g_cnt[dst[i]], 1);
}

__global__ void inv_kernel(int n) {
    int i = blockIdx.x * blockDim.x + threadIdx.x;
    if (i < n) {
        g_inv[i] = 1.0f / fmaxf((float)g_cnt[i], 1.0f);
        g_aq0[i] = 0.f;
        g_aq1[i] = 0.f;
    }
}

// ---------------------------------------------------------------------------
__global__ void scatter_kernel(const float* __restrict__ x,
                               const int* __restrict__ src,
                               const int* __restrict__ dst, int e) {
    int w    = (blockIdx.x * blockDim.x + threadIdx.x) >> 5;
    int lane = threadIdx.x & 31;
    if (w >= e) return;
    int s = __ldg(src + w);
    int d = __ldg(dst + w);
    float4 v = *(const float4*)(x + (size_t)s * DD + lane * 4);
    atomicAdd((float4*)(g_agg + (size_t)d * DD + lane * 4), v);
}

// ---------------------------------------------------------------------------
__global__ void scatter2_kernel(const int* __restrict__ src,
                                const int* __restrict__ dst, int e) {
    int i = blockIdx.x * blockDim.x + threadIdx.x;
    if (i >= e) return;
    int s = __ldg(src + i);
    int d = __ldg(dst + i);
    atomicAdd(&g_aq0[d], g_q0[s]);
    atomicAdd(&g_aq1[d], g_q1[s]);
}

// ---------------------------------------------------------------------------
// u/v projections, one warp per output row.
// ---------------------------------------------------------------------------
__global__ void uv_kernel(const float* __restrict__ W2l,
                          const float* __restrict__ W2r,
                          const float* __restrict__ b2,
                          const float* __restrict__ Wlin,
                          const float* __restrict__ blin) {
    int w    = (blockIdx.x * blockDim.x + threadIdx.x) >> 5;
    int lane = threadIdx.x & 31;
    if (w >= DD) return;
    const float* rl = W2l + (size_t)w * DD;
    const float* rr = W2r + (size_t)w * DD;
    float u0 = 0.f, u1 = 0.f, v0 = 0.f, v1 = 0.f;
    #pragma unroll
    for (int jj = 0; jj < 4; jj++) {
        int j = lane + 32 * jj;
        float a  = __ldg(rl + j);
        float b  = __ldg(rr + j);
        float w0 = __ldg(Wlin + j);
        float w1 = __ldg(Wlin + DD + j);
        u0 = fmaf(a, w0, u0);
        u1 = fmaf(a, w1, u1);
        v0 = fmaf(b, w0, v0);
        v1 = fmaf(b, w1, v1);
    }
    #pragma unroll
    for (int o = 16; o > 0; o >>= 1) {
        u0 += __shfl_down_sync(0xFFFFFFFFu, u0, o);
        u1 += __shfl_down_sync(0xFFFFFFFFu, u1, o);
        v0 += __shfl_down_sync(0xFFFFFFFFu, v0, o);
        v1 += __shfl_down_sync(0xFFFFFFFFu, v1, o);
    }
    if (lane == 0) {
        g_u0[w] = u0; g_u1[w] = u1; g_v0[w] = v0; g_v1[w] = v1;
    }
    if (w == 0) {
        float c = 0.f;
        #pragma unroll
        for (int jj = 0; jj < 4; jj++) {
            int j = lane + 32 * jj;
            c = fmaf(__ldg(b2 + j), __ldg(Wlin + j) + __ldg(Wlin + DD + j), c);
        }
        #pragma unroll
        for (int o = 16; o > 0; o >>= 1)
            c += __shfl_down_sync(0xFFFFFFFFu, c, o);
        if (lane == 0) g_c = c + __ldg(blin);
    }
}

// ---------------------------------------------------------------------------
// bf16-split tensor-core GEMM (mma.sync m16n8k16) fused with projection:
//   x1row = relu( (agg*inv) @ W1l + b1 + emb @ W1r )     (registers only)
//   q0..xv1 = x1row · {u0,u1,v0,v1}
// Split: v = hi + lo (hi = truncated-to-bf16), D = Ah·Wh + Ah·Wl + Al·Wh.
// ---------------------------------------------------------------------------
#define GT 512
#define PADK 136                   // bf16 elems per row (272B, conflict-free)
#define SM_WHI 0                   // [256][136] bf16 = 69632
#define SM_WLO 69632
#define SM_AHI 139264              // [128][136] bf16 = 34816
#define SM_ALO 174080
#define SM_PART 208896             // float[4][128][4] = 8192
#define SM_BIAS 217088             // 512
#define SM_PROJ 217600             // 4 x 512
#define SMEM_TOTAL 219648

__device__ __forceinline__ uint32_t smem_u32(const void* p) {
    uint32_t a;
    asm("{ .reg .u64 t; cvta.to.shared.u64 t, %1; cvt.u32.u64 %0, t; }"
        : "=r"(a) : "l"(p));
    return a;
}

// Split two floats into packed bf16x2 hi (truncation) and lo (residual, RN).
__device__ __forceinline__ void split2(float a, float b,
                                       uint32_t& hi2, uint32_t& lo2) {
    uint32_t ia = __float_as_uint(a) & 0xFFFF0000u;
    uint32_t ib = __float_as_uint(b) & 0xFFFF0000u;
    hi2 = (ia >> 16) | ib;                       // lo half = a, hi half = b
    float la = a - __uint_as_float(ia);
    float lb = b - __uint_as_float(ib);
    asm("cvt.rn.bf16x2.f32 %0, %1, %2;" : "=r"(lo2) : "f"(lb), "f"(la));
}

__device__ __forceinline__ void ldsm_x4(uint32_t* r, uint32_t addr) {
    asm volatile("ldmatrix.sync.aligned.m8n8.x4.shared.b16 {%0,%1,%2,%3}, [%4];"
        : "=r"(r[0]), "=r"(r[1]), "=r"(r[2]), "=r"(r[3]) : "r"(addr));
}

__device__ __forceinline__ void ldsm_x2t(uint32_t* r, uint32_t addr) {
    asm volatile("ldmatrix.sync.aligned.m8n8.x2.trans.shared.b16 {%0,%1}, [%2];"
        : "=r"(r[0]), "=r"(r[1]) : "r"(addr));
}

__device__ __forceinline__ void mma_bf16(float* d, const uint32_t* a,
                                         const uint32_t* b) {
    asm volatile("mma.sync.aligned.m16n8k16.row.col.f32.bf16.bf16.f32 "
        "{%0,%1,%2,%3}, {%4,%5,%6,%7}, {%8,%9}, {%0,%1,%2,%3};"
        : "+f"(d[0]), "+f"(d[1]), "+f"(d[2]), "+f"(d[3])
        : "r"(a[0]), "r"(a[1]), "r"(a[2]), "r"(a[3]), "r"(b[0]), "r"(b[1]));
}

__global__ __launch_bounds__(GT, 1)
void sage_gemm_mma(const float* __restrict__ agg,
                   const float* __restrict__ xin,
                   const float* __restrict__ Wl,
                   const float* __restrict__ bias,
                   const float* __restrict__ Wr,
                   int n) {
    extern __shared__ char smem[];
    const uint32_t sb = smem_u32(smem);
    const int tid  = threadIdx.x;
    const int lane = tid & 31;
    const int wid  = tid >> 5;
    const int mi   = wid >> 2;        // m-block 0..3 (rows mi*32)
    const int ni   = wid & 3;         // n-block 0..3 (cols ni*32)

    // Stage W_cat = [W1l ; W1r] as bf16 hi/lo, [k=256][n=128] padded rows.
    for (int i = tid; i < 256 * 32; i += GT) {
        int row = i >> 5, c4 = i & 31;
        const float* wsrc = (row < 128) ? (Wl + (size_t)row * 128)
                                        : (Wr + (size_t)(row - 128) * 128);
        float4 v = ((const float4*)wsrc)[c4];
        uint32_t h01, l01, h23, l23;
        split2(v.x, v.y, h01, l01);
        split2(v.z, v.w, h23, l23);
        *(uint2*)(smem + SM_WHI + row * 272 + c4 * 8) = make_uint2(h01, h23);
        *(uint2*)(smem + SM_WLO + row * 272 + c4 * 8) = make_uint2(l01, l23);
    }
    if (tid < DD) {
        ((float*)(smem + SM_BIAS))[tid]        = bias[tid];
        ((float*)(smem + SM_PROJ))[tid]        = g_u0[tid];
        ((float*)(smem + SM_PROJ + 512))[tid]  = g_u1[tid];
        ((float*)(smem + SM_PROJ + 1024))[tid] = g_v0[tid];
        ((float*)(smem + SM_PROJ + 1536))[tid] = g_v1[tid];
    }
    __syncthreads();

    const int ntiles = (n + 127) >> 7;
    for (int t = blockIdx.x; t < ntiles; t += gridDim.x) {
        const int base = t << 7;

        float D[2][4][4];
        #pragma unroll
        for (int mt = 0; mt < 2; mt++)
            #pragma unroll
            for (int nt = 0; nt < 4; nt++)
                #pragma unroll
                for (int j = 0; j < 4; j++) D[mt][nt][j] = 0.f;

        #pragma unroll
        for (int h = 0; h < 2; h++) {
            __syncthreads();   // A buffers free (prior half / prior tile done)
            // Stage A half: h=0 -> agg*inv, h=1 -> emb. [128][128] hi/lo.
            for (int i = tid; i < 128 * 32; i += GT) {
                int row = i >> 5, c4 = i & 31;
                int gr = base + row;
                float4 v = make_float4(0.f, 0.f, 0.f, 0.f);
                if (gr < n) {
                    if (h == 0) {
                        v = ((const float4*)(agg + (size_t)gr * DD))[c4];
                        float inv = g_inv[gr];
                        v.x *= inv; v.y *= inv; v.z *= inv; v.w *= inv;
                    } else {
                        v = ((const float4*)(xin + (size_t)gr * DD))[c4];
                    }
                }
                uint32_t h01, l01, h23, l23;
                split2(v.x, v.y, h01, l01);
                split2(v.z, v.w, h23, l23);
                *(uint2*)(smem + SM_AHI + row * 272 + c4 * 8) = make_uint2(h01, h23);
                *(uint2*)(smem + SM_ALO + row * 272 + c4 * 8) = make_uint2(l01, l23);
            }
            __syncthreads();

            const uint32_t wrow0 = h * 128;
            #pragma unroll
            for (int ks = 0; ks < 8; ks++) {
                const int kb = ks * 16;
                // B fragments (shared across m-tiles)
                uint32_t bh[4][2], bl[4][2];
                uint32_t bko = (wrow0 + kb + (lane & 15)) * 272;
                #pragma unroll
                for (int nt = 0; nt < 4; nt++) {
                    uint32_t cb2 = (ni * 32 + nt * 8) * 2;
                    ldsm_x2t(bh[nt], sb + SM_WHI + bko + cb2);
                    ldsm_x2t(bl[nt], sb + SM_WLO + bko + cb2);
                }
                // A fragments
                uint32_t ah[2][4], al[2][4];
                uint32_t arow = (lane & 7) + ((lane >> 3) & 1) * 8;
                uint32_t akc  = kb + (lane >> 4) * 8;
                #pragma unroll
                for (int mt = 0; mt < 2; mt++) {
                    uint32_t off = (mi * 32 + mt * 16 + arow) * 272 + akc * 2;
                    ldsm_x4(ah[mt], sb + SM_AHI + off);
                    ldsm_x4(al[mt], sb + SM_ALO + off);
                }
                #pragma unroll
                for (int mt = 0; mt < 2; mt++)
                    #pragma unroll
                    for (int nt = 0; nt < 4; nt++) {
                        mma_bf16(D[mt][nt], ah[mt], bh[nt]);
                        mma_bf16(D[mt][nt], ah[mt], bl[nt]);
                        mma_bf16(D[mt][nt], al[mt], bh[nt]);
                    }
            }
        }

        // Epilogue: relu+bias, project to 4 scalars, reduce.
        // D frag mapping: thread(g=lane>>2, c=lane&3):
        //   d0=D[g][2c], d1=D[g][2c+1], d2=D[g+8][2c], d3=D[g+8][2c+1]
        const float* bs  = (const float*)(smem + SM_BIAS);
        const float* pu0 = (const float*)(smem + SM_PROJ);
        const float* pu1 = (const float*)(smem + SM_PROJ + 512);
        const float* pv0 = (const float*)(smem + SM_PROJ + 1024);
        const float* pv1 = (const float*)(smem + SM_PROJ + 1536);
        float* part = (float*)(smem + SM_PART);
        const int g = lane >> 2, c = lane & 3;

        #pragma unroll
        for (int mt = 0; mt < 2; mt++) {
            float pl[4] = {0.f, 0.f, 0.f, 0.f};
            float ph[4] = {0.f, 0.f, 0.f, 0.f};
            #pragma unroll
            for (int nt = 0; nt < 4; nt++) {
                int col = ni * 32 + nt * 8 + 2 * c;
                float b0 = bs[col], b1 = bs[col + 1];
                float s00 = fmaxf(D[mt][nt][0] + b0, 0.f);
                float s01 = fmaxf(D[mt][nt][1] + b1, 0.f);
                float s10 = fmaxf(D[mt][nt][2] + b0, 0.f);
                float s11 = fmaxf(D[mt][nt][3] + b1, 0.f);
                float a0, a1;
                a0 = pu0[col]; a1 = pu0[col + 1];
                pl[0] += s00 * a0 + s01 * a1;  ph[0] += s10 * a0 + s11 * a1;
                a0 = pu1[col]; a1 = pu1[col + 1];
                pl[1] += s00 * a0 + s01 * a1;  ph[1] += s10 * a0 + s11 * a1;
                a0 = pv0[col]; a1 = pv0[col + 1];
                pl[2] += s00 * a0 + s01 * a1;  ph[2] += s10 * a0 + s11 * a1;
                a0 = pv1[col]; a1 = pv1[col + 1];
                pl[3] += s00 * a0 + s01 * a1;  ph[3] += s10 * a0 + s11 * a1;
            }
            #pragma unroll
            for (int o = 1; o <= 2; o <<= 1) {
                #pragma unroll
                for (int j = 0; j < 4; j++) {
                    pl[j] += __shfl_xor_sync(0xFFFFFFFFu, pl[j], o);
                    ph[j] += __shfl_xor_sync(0xFFFFFFFFu, ph[j], o);
                }
            }
            if (c == 0) {
                int rl = mi * 32 + mt * 16 + g;
                int rh = rl + 8;
                #pragma unroll
                for (int j = 0; j < 4; j++) {
                    part[j * 512 + rl * 4 + ni] = pl[j];
                    part[j * 512 + rh * 4 + ni] = ph[j];
                }
            }
        }
        __syncthreads();
        if (tid < 128) {
            int gr = base + tid;
            if (gr < n) {
                float s[4];
                #pragma unroll
                for (int j = 0; j < 4; j++) {
                    const float* p = part + j * 512 + tid * 4;
                    s[j] = p[0] + p[1] + p[2] + p[3];
                }
                g_q0 [gr] = s[0];
                g_q1 [gr] = s[1];
                g_xv0[gr] = s[2];
                g_xv1[gr] = s[3];
            }
        }
        // next tile's first __syncthreads (top of h-loop) protects part/A
    }
}

// ---------------------------------------------------------------------------
__global__ void fold_kernel(int n) {
    int v = blockIdx.x * blockDim.x + threadIdx.x;
    if (v >= n) return;
    float inv = g_inv[v];
    g_r0[v] = fmaf(inv, g_aq0[v], g_xv0[v]);
    g_r1[v] = fmaf(inv, g_aq1[v], g_xv1[v]);
}

// ---------------------------------------------------------------------------
__global__ void predict_kernel(const int* __restrict__ s,
                               const int* __restrict__ d,
                               float* __restrict__ out, int L) {
    int l = blockIdx.x * blockDim.x + threadIdx.x;
    if (l >= L) return;
    out[l] = g_r0[__ldg(s + l)] + g_r1[__ldg(d + l)] + g_c;
}

// ---------------------------------------------------------------------------
extern "C" void kernel_launch(void* const* d_in, const int* in_sizes, int n_in,
                              void* d_out, int out_size) {
    const int*   ei   = (const int*)d_in[0];
    const int*   eli  = (const int*)d_in[1];
    const float* emb  = (const float*)d_in[2];
    const float* W1l  = (const float*)d_in[3];
    const float* b1   = (const float*)d_in[4];
    const float* W1r  = (const float*)d_in[5];
    const float* W2l  = (const float*)d_in[6];
    const float* b2   = (const float*)d_in[7];
    const float* W2r  = (const float*)d_in[8];
    const float* Wlin = (const float*)d_in[9];
    const float* blin = (const float*)d_in[10];
    float*       out  = (float*)d_out;

    const int E = in_sizes[0] / 2;
    const int L = in_sizes[1] / 2;
    const int N = in_sizes[2] / DD;

    const int* src = ei;
    const int* dst = ei + E;
    const int* ls  = eli;
    const int* ld  = eli + L;

    void* p_agg = nullptr; cudaGetSymbolAddress(&p_agg, g_agg);
    void* p_cnt = nullptr; cudaGetSymbolAddress(&p_cnt, g_cnt);
    float* agg = (float*)p_agg;

    cudaFuncSetAttribute(sage_gemm_mma,
                         cudaFuncAttributeMaxDynamicSharedMemorySize,
                         SMEM_TOTAL);

    const int scatter_blocks = ((size_t)E * 32 + 255) / 256;

    // Setup
    cudaMemsetAsync(p_cnt, 0, sizeof(int) * (size_t)N);
    cudaMemsetAsync(p_agg, 0, sizeof(float) * (size_t)N * DD);
    deg_kernel<<<(E + 255) / 256, 256>>>(dst, E);
    inv_kernel<<<(N + 255) / 256, 256>>>(N);
    uv_kernel<<<16, 256>>>(W2l, W2r, b2, Wlin, blin);

    // Layer 1 aggregation + tensor-core fused GEMM/projection
    scatter_kernel<<<scatter_blocks, 256>>>(emb, src, dst, E);
    sage_gemm_mma<<<148, GT, SMEM_TOTAL>>>(agg, emb, W1l, b1, W1r, N);

    // Layer 2: scalar scatter + fold + predict
    scatter2_kernel<<<(E + 255) / 256, 256>>>(src, dst, E);
    fold_kernel<<<(N + 255) / 256, 256>>>(N);
    predict_kernel<<<(L + 255) / 256, 256>>>(ls, ld, out, L);
}

// round 14
// speedup vs baseline: 2.6453x; 1.1190x over previous
#include <cuda_runtime.h>
#include <cstddef>
#include <cstdint>

#define NN 100000
#define DD 128

__device__ float g_agg[(size_t)NN * DD];   // layer-1 neighbor sums
__device__ float g_q0 [NN], g_q1 [NN];     // x1·u0, x1·u1
__device__ float g_xv0[NN], g_xv1[NN];     // x1·v0, x1·v1
__device__ float g_aq0[NN], g_aq1[NN];     // scattered q sums
__device__ float g_r0 [NN], g_r1 [NN];
__device__ float g_inv[NN];
__device__ int   g_cnt[NN];
__device__ float g_u0[DD], g_u1[DD], g_v0[DD], g_v1[DD];
__device__ float g_c;

// ---------------------------------------------------------------------------
__global__ void inv_kernel(int n) {
    int i = blockIdx.x * blockDim.x + threadIdx.x;
    if (i < n) {
        g_inv[i] = 1.0f / fmaxf((float)g_cnt[i], 1.0f);
        g_aq0[i] = 0.f;
        g_aq1[i] = 0.f;
    }
}

// ---------------------------------------------------------------------------
// Scatter, 4 edges per warp (MLP-batched), with degree counting folded in.
// ---------------------------------------------------------------------------
#define EPW 4
__global__ void scatter_kernel(const float* __restrict__ x,
                               const int* __restrict__ src,
                               const int* __restrict__ dst, int e) {
    int w    = (blockIdx.x * blockDim.x + threadIdx.x) >> 5;
    int lane = threadIdx.x & 31;
    int e0   = w * EPW;
    if (e0 >= e) return;
    int ne = min(EPW, e - e0);

    int s[EPW], d[EPW];
    #pragma unroll
    for (int i = 0; i < EPW; i++) {
        int idx = min(e0 + i, e - 1);
        s[i] = __ldg(src + idx);
        d[i] = __ldg(dst + idx);
    }
    // 4 independent wide loads in flight
    float4 v[EPW];
    #pragma unroll
    for (int i = 0; i < EPW; i++)
        v[i] = *(const float4*)(x + (size_t)s[i] * DD + lane * 4);
    // degree counts (merged deg_kernel)
    if (lane == 0) {
        #pragma unroll
        for (int i = 0; i < EPW; i++)
            if (i < ne) atomicAdd(&g_cnt[d[i]], 1);
    }
    // fire-and-forget reductions
    #pragma unroll
    for (int i = 0; i < EPW; i++)
        if (i < ne)
            atomicAdd((float4*)(g_agg + (size_t)d[i] * DD + lane * 4), v[i]);
}

// ---------------------------------------------------------------------------
__global__ void scatter2_kernel(const int* __restrict__ src,
                                const int* __restrict__ dst, int e) {
    int i = blockIdx.x * blockDim.x + threadIdx.x;
    if (i >= e) return;
    int s = __ldg(src + i);
    int d = __ldg(dst + i);
    atomicAdd(&g_aq0[d], g_q0[s]);
    atomicAdd(&g_aq1[d], g_q1[s]);
}

// ---------------------------------------------------------------------------
// u/v projections, one warp per output row.
// ---------------------------------------------------------------------------
__global__ void uv_kernel(const float* __restrict__ W2l,
                          const float* __restrict__ W2r,
                          const float* __restrict__ b2,
                          const float* __restrict__ Wlin,
                          const float* __restrict__ blin) {
    int w    = (blockIdx.x * blockDim.x + threadIdx.x) >> 5;
    int lane = threadIdx.x & 31;
    if (w >= DD) return;
    const float* rl = W2l + (size_t)w * DD;
    const float* rr = W2r + (size_t)w * DD;
    float u0 = 0.f, u1 = 0.f, v0 = 0.f, v1 = 0.f;
    #pragma unroll
    for (int jj = 0; jj < 4; jj++) {
        int j = lane + 32 * jj;
        float a  = __ldg(rl + j);
        float b  = __ldg(rr + j);
        float w0 = __ldg(Wlin + j);
        float w1 = __ldg(Wlin + DD + j);
        u0 = fmaf(a, w0, u0);
        u1 = fmaf(a, w1, u1);
        v0 = fmaf(b, w0, v0);
        v1 = fmaf(b, w1, v1);
    }
    #pragma unroll
    for (int o = 16; o > 0; o >>= 1) {
        u0 += __shfl_down_sync(0xFFFFFFFFu, u0, o);
        u1 += __shfl_down_sync(0xFFFFFFFFu, u1, o);
        v0 += __shfl_down_sync(0xFFFFFFFFu, v0, o);
        v1 += __shfl_down_sync(0xFFFFFFFFu, v1, o);
    }
    if (lane == 0) {
        g_u0[w] = u0; g_u1[w] = u1; g_v0[w] = v0; g_v1[w] = v1;
    }
    if (w == 0) {
        float c = 0.f;
        #pragma unroll
        for (int jj = 0; jj < 4; jj++) {
            int j = lane + 32 * jj;
            c = fmaf(__ldg(b2 + j), __ldg(Wlin + j) + __ldg(Wlin + DD + j), c);
        }
        #pragma unroll
        for (int o = 16; o > 0; o >>= 1)
            c += __shfl_down_sync(0xFFFFFFFFu, c, o);
        if (lane == 0) g_c = c + __ldg(blin);
    }
}

// ---------------------------------------------------------------------------
// bf16-split tensor-core GEMM (mma.sync m16n8k16) fused with projection:
//   x1row = relu( (agg*inv) @ W1l + b1 + emb @ W1r )     (registers only)
//   q0..xv1 = x1row · {u0,u1,v0,v1}
// Split: v = hi + lo (hi = truncated-to-bf16), D = Ah·Wh + Ah·Wl + Al·Wh.
// ---------------------------------------------------------------------------
#define GT 512
#define SM_WHI 0                   // [256][136] bf16 = 69632
#define SM_WLO 69632
#define SM_AHI 139264              // [128][136] bf16 = 34816
#define SM_ALO 174080
#define SM_PART 208896             // float[4][128][4] = 8192
#define SM_BIAS 217088             // 512
#define SM_PROJ 217600             // 4 x 512
#define SMEM_TOTAL 219648

__device__ __forceinline__ uint32_t smem_u32(const void* p) {
    uint32_t a;
    asm("{ .reg .u64 t; cvta.to.shared.u64 t, %1; cvt.u32.u64 %0, t; }"
        : "=r"(a) : "l"(p));
    return a;
}

__device__ __forceinline__ void split2(float a, float b,
                                       uint32_t& hi2, uint32_t& lo2) {
    uint32_t ia = __float_as_uint(a) & 0xFFFF0000u;
    uint32_t ib = __float_as_uint(b) & 0xFFFF0000u;
    hi2 = (ia >> 16) | ib;
    float la = a - __uint_as_float(ia);
    float lb = b - __uint_as_float(ib);
    asm("cvt.rn.bf16x2.f32 %0, %1, %2;" : "=r"(lo2) : "f"(lb), "f"(la));
}

__device__ __forceinline__ void ldsm_x4(uint32_t* r, uint32_t addr) {
    asm volatile("ldmatrix.sync.aligned.m8n8.x4.shared.b16 {%0,%1,%2,%3}, [%4];"
        : "=r"(r[0]), "=r"(r[1]), "=r"(r[2]), "=r"(r[3]) : "r"(addr));
}

__device__ __forceinline__ void ldsm_x2t(uint32_t* r, uint32_t addr) {
    asm volatile("ldmatrix.sync.aligned.m8n8.x2.trans.shared.b16 {%0,%1}, [%2];"
        : "=r"(r[0]), "=r"(r[1]) : "r"(addr));
}

__device__ __forceinline__ void mma_bf16(float* d, const uint32_t* a,
                                         const uint32_t* b) {
    asm volatile("mma.sync.aligned.m16n8k16.row.col.f32.bf16.bf16.f32 "
        "{%0,%1,%2,%3}, {%4,%5,%6,%7}, {%8,%9}, {%0,%1,%2,%3};"
        : "+f"(d[0]), "+f"(d[1]), "+f"(d[2]), "+f"(d[3])
        : "r"(a[0]), "r"(a[1]), "r"(a[2]), "r"(a[3]), "r"(b[0]), "r"(b[1]));
}

__global__ __launch_bounds__(GT, 1)
void sage_gemm_mma(const float* __restrict__ agg,
                   const float* __restrict__ xin,
                   const float* __restrict__ Wl,
                   const float* __restrict__ bias,
                   const float* __restrict__ Wr,
                   int n) {
    extern __shared__ char smem[];
    const uint32_t sb = smem_u32(smem);
    const int tid  = threadIdx.x;
    const int lane = tid & 31;
    const int wid  = tid >> 5;
    const int mi   = wid >> 2;
    const int ni   = wid & 3;

    for (int i = tid; i < 256 * 32; i += GT) {
        int row = i >> 5, c4 = i & 31;
        const float* wsrc = (row < 128) ? (Wl + (size_t)row * 128)
                                        : (Wr + (size_t)(row - 128) * 128);
        float4 v = ((const float4*)wsrc)[c4];
        uint32_t h01, l01, h23, l23;
        split2(v.x, v.y, h01, l01);
        split2(v.z, v.w, h23, l23);
        *(uint2*)(smem + SM_WHI + row * 272 + c4 * 8) = make_uint2(h01, h23);
        *(uint2*)(smem + SM_WLO + row * 272 + c4 * 8) = make_uint2(l01, l23);
    }
    if (tid < DD) {
        ((float*)(smem + SM_BIAS))[tid]        = bias[tid];
        ((float*)(smem + SM_PROJ))[tid]        = g_u0[tid];
        ((float*)(smem + SM_PROJ + 512))[tid]  = g_u1[tid];
        ((float*)(smem + SM_PROJ + 1024))[tid] = g_v0[tid];
        ((float*)(smem + SM_PROJ + 1536))[tid] = g_v1[tid];
    }
    __syncthreads();

    const int ntiles = (n + 127) >> 7;
    for (int t = blockIdx.x; t < ntiles; t += gridDim.x) {
        const int base = t << 7;

        float D[2][4][4];
        #pragma unroll
        for (int mt = 0; mt < 2; mt++)
            #pragma unroll
            for (int nt = 0; nt < 4; nt++)
                #pragma unroll
                for (int j = 0; j < 4; j++) D[mt][nt][j] = 0.f;

        #pragma unroll
        for (int h = 0; h < 2; h++) {
            __syncthreads();
            for (int i = tid; i < 128 * 32; i += GT) {
                int row = i >> 5, c4 = i & 31;
                int gr = base + row;
                float4 v = make_float4(0.f, 0.f, 0.f, 0.f);
                if (gr < n) {
                    if (h == 0) {
                        v = ((const float4*)(agg + (size_t)gr * DD))[c4];
                        float inv = g_inv[gr];
                        v.x *= inv; v.y *= inv; v.z *= inv; v.w *= inv;
                    } else {
                        v = ((const float4*)(xin + (size_t)gr * DD))[c4];
                    }
                }
                uint32_t h01, l01, h23, l23;
                split2(v.x, v.y, h01, l01);
                split2(v.z, v.w, h23, l23);
                *(uint2*)(smem + SM_AHI + row * 272 + c4 * 8) = make_uint2(h01, h23);
                *(uint2*)(smem + SM_ALO + row * 272 + c4 * 8) = make_uint2(l01, l23);
            }
            __syncthreads();

            const uint32_t wrow0 = h * 128;
            #pragma unroll
            for (int ks = 0; ks < 8; ks++) {
                const int kb = ks * 16;
                uint32_t bh[4][2], bl[4][2];
                uint32_t bko = (wrow0 + kb + (lane & 15)) * 272;
                #pragma unroll
                for (int nt = 0; nt < 4; nt++) {
                    uint32_t cb2 = (ni * 32 + nt * 8) * 2;
                    ldsm_x2t(bh[nt], sb + SM_WHI + bko + cb2);
                    ldsm_x2t(bl[nt], sb + SM_WLO + bko + cb2);
                }
                uint32_t ah[2][4], al[2][4];
                uint32_t arow = (lane & 7) + ((lane >> 3) & 1) * 8;
                uint32_t akc  = kb + (lane >> 4) * 8;
                #pragma unroll
                for (int mt = 0; mt < 2; mt++) {
                    uint32_t off = (mi * 32 + mt * 16 + arow) * 272 + akc * 2;
                    ldsm_x4(ah[mt], sb + SM_AHI + off);
                    ldsm_x4(al[mt], sb + SM_ALO + off);
                }
                #pragma unroll
                for (int mt = 0; mt < 2; mt++)
                    #pragma unroll
                    for (int nt = 0; nt < 4; nt++) {
                        mma_bf16(D[mt][nt], ah[mt], bh[nt]);
                        mma_bf16(D[mt][nt], ah[mt], bl[nt]);
                        mma_bf16(D[mt][nt], al[mt], bh[nt]);
                    }
            }
        }

        const float* bs  = (const float*)(smem + SM_BIAS);
        const float* pu0 = (const float*)(smem + SM_PROJ);
        const float* pu1 = (const float*)(smem + SM_PROJ + 512);
        const float* pv0 = (const float*)(smem + SM_PROJ + 1024);
        const float* pv1 = (const float*)(smem + SM_PROJ + 1536);
        float* part = (float*)(smem + SM_PART);
        const int g = lane >> 2, c = lane & 3;

        #pragma unroll
        for (int mt = 0; mt < 2; mt++) {
            float pl[4] = {0.f, 0.f, 0.f, 0.f};
            float ph[4] = {0.f, 0.f, 0.f, 0.f};
            #pragma unroll
            for (int nt = 0; nt < 4; nt++) {
                int col = ni * 32 + nt * 8 + 2 * c;
                float b0 = bs[col], b1 = bs[col + 1];
                float s00 = fmaxf(D[mt][nt][0] + b0, 0.f);
                float s01 = fmaxf(D[mt][nt][1] + b1, 0.f);
                float s10 = fmaxf(D[mt][nt][2] + b0, 0.f);
                float s11 = fmaxf(D[mt][nt][3] + b1, 0.f);
                float a0, a1;
                a0 = pu0[col]; a1 = pu0[col + 1];
                pl[0] += s00 * a0 + s01 * a1;  ph[0] += s10 * a0 + s11 * a1;
                a0 = pu1[col]; a1 = pu1[col + 1];
                pl[1] += s00 * a0 + s01 * a1;  ph[1] += s10 * a0 + s11 * a1;
                a0 = pv0[col]; a1 = pv0[col + 1];
                pl[2] += s00 * a0 + s01 * a1;  ph[2] += s10 * a0 + s11 * a1;
                a0 = pv1[col]; a1 = pv1[col + 1];
                pl[3] += s00 * a0 + s01 * a1;  ph[3] += s10 * a0 + s11 * a1;
            }
            #pragma unroll
            for (int o = 1; o <= 2; o <<= 1) {
                #pragma unroll
                for (int j = 0; j < 4; j++) {
                    pl[j] += __shfl_xor_sync(0xFFFFFFFFu, pl[j], o);
                    ph[j] += __shfl_xor_sync(0xFFFFFFFFu, ph[j], o);
                }
            }
            if (c == 0) {
                int rl = mi * 32 + mt * 16 + g;
                int rh = rl + 8;
                #pragma unroll
                for (int j = 0; j < 4; j++) {
                    part[j * 512 + rl * 4 + ni] = pl[j];
                    part[j * 512 + rh * 4 + ni] = ph[j];
                }
            }
        }
        __syncthreads();
        if (tid < 128) {
            int gr = base + tid;
            if (gr < n) {
                float s[4];
                #pragma unroll
                for (int j = 0; j < 4; j++) {
                    const float* p = part + j * 512 + tid * 4;
                    s[j] = p[0] + p[1] + p[2] + p[3];
                }
                g_q0 [gr] = s[0];
                g_q1 [gr] = s[1];
                g_xv0[gr] = s[2];
                g_xv1[gr] = s[3];
            }
        }
    }
}

// ---------------------------------------------------------------------------
__global__ void fold_kernel(int n) {
    int v = blockIdx.x * blockDim.x + threadIdx.x;
    if (v >= n) return;
    float inv = g_inv[v];
    g_r0[v] = fmaf(inv, g_aq0[v], g_xv0[v]);
    g_r1[v] = fmaf(inv, g_aq1[v], g_xv1[v]);
}

// ---------------------------------------------------------------------------
__global__ void predict_kernel(const int* __restrict__ s,
                               const int* __restrict__ d,
                               float* __restrict__ out, int L) {
    int l = blockIdx.x * blockDim.x + threadIdx.x;
    if (l >= L) return;
    out[l] = g_r0[__ldg(s + l)] + g_r1[__ldg(d + l)] + g_c;
}

// ---------------------------------------------------------------------------
extern "C" void kernel_launch(void* const* d_in, const int* in_sizes, int n_in,
                              void* d_out, int out_size) {
    const int*   ei   = (const int*)d_in[0];
    const int*   eli  = (const int*)d_in[1];
    const float* emb  = (const float*)d_in[2];
    const float* W1l  = (const float*)d_in[3];
    const float* b1   = (const float*)d_in[4];
    const float* W1r  = (const float*)d_in[5];
    const float* W2l  = (const float*)d_in[6];
    const float* b2   = (const float*)d_in[7];
    const float* W2r  = (const float*)d_in[8];
    const float* Wlin = (const float*)d_in[9];
    const float* blin = (const float*)d_in[10];
    float*       out  = (float*)d_out;

    const int E = in_sizes[0] / 2;
    const int L = in_sizes[1] / 2;
    const int N = in_sizes[2] / DD;

    const int* src = ei;
    const int* dst = ei + E;
    const int* ls  = eli;
    const int* ld  = eli + L;

    void* p_agg = nullptr; cudaGetSymbolAddress(&p_agg, g_agg);
    void* p_cnt = nullptr; cudaGetSymbolAddress(&p_cnt, g_cnt);
    float* agg = (float*)p_agg;

    cudaFuncSetAttribute(sage_gemm_mma,
                         cudaFuncAttributeMaxDynamicSharedMemorySize,
                         SMEM_TOTAL);

    const int nwarps = (E + EPW - 1) / EPW;
    const int scatter_blocks = ((size_t)nwarps * 32 + 255) / 256;

    // Setup
    cudaMemsetAsync(p_cnt, 0, sizeof(int) * (size_t)N);
    cudaMemsetAsync(p_agg, 0, sizeof(float) * (size_t)N * DD);
    uv_kernel<<<16, 256>>>(W2l, W2r, b2, Wlin, blin);

    // Layer 1 aggregation (with fused degree count) + tensor-core GEMM
    scatter_kernel<<<scatter_blocks, 256>>>(emb, src, dst, E);
    inv_kernel<<<(N + 255) / 256, 256>>>(N);
    sage_gemm_mma<<<148, GT, SMEM_TOTAL>>>(agg, emb, W1l, b1, W1r, N);

    // Layer 2: scalar scatter + fold + predict
    scatter2_kernel<<<(E + 255) / 256, 256>>>(src, dst, E);
    fold_kernel<<<(N + 255) / 256, 256>>>(N);
    predict_kernel<<<(L + 255) / 256, 256>>>(ls, ld, out, L);
}

// round 15
// speedup vs baseline: 2.8006x; 1.0587x over previous
#include <cuda_runtime.h>
#include <cstddef>
#include <cstdint>

#define NN 100000
#define DD 128

__device__ float g_agg[(size_t)NN * DD];   // layer-1 neighbor sums
__device__ float g_q0 [NN], g_q1 [NN];     // x1·u0, x1·u1
__device__ float g_xv0[NN], g_xv1[NN];     // x1·v0, x1·v1
__device__ float g_aq0[NN], g_aq1[NN];     // scattered q sums
__device__ float g_r0 [NN], g_r1 [NN];
__device__ float g_inv[NN];
__device__ int   g_cnt[NN];
__device__ float g_u0[DD], g_u1[DD], g_v0[DD], g_v1[DD];
__device__ float g_c;

// ---------------------------------------------------------------------------
__global__ void inv_kernel(int n) {
    int i = blockIdx.x * blockDim.x + threadIdx.x;
    if (i < n) {
        g_inv[i] = 1.0f / fmaxf((float)g_cnt[i], 1.0f);
        g_aq0[i] = 0.f;
        g_aq1[i] = 0.f;
    }
}

// ---------------------------------------------------------------------------
// Scatter, 4 edges per warp (MLP-batched), with degree counting folded in.
// ---------------------------------------------------------------------------
#define EPW 4
__global__ void scatter_kernel(const float* __restrict__ x,
                               const int* __restrict__ src,
                               const int* __restrict__ dst, int e) {
    int w    = (blockIdx.x * blockDim.x + threadIdx.x) >> 5;
    int lane = threadIdx.x & 31;
    int e0   = w * EPW;
    if (e0 >= e) return;
    int ne = min(EPW, e - e0);

    int s[EPW], d[EPW];
    #pragma unroll
    for (int i = 0; i < EPW; i++) {
        int idx = min(e0 + i, e - 1);
        s[i] = __ldg(src + idx);
        d[i] = __ldg(dst + idx);
    }
    float4 v[EPW];
    #pragma unroll
    for (int i = 0; i < EPW; i++)
        v[i] = *(const float4*)(x + (size_t)s[i] * DD + lane * 4);
    if (lane == 0) {
        #pragma unroll
        for (int i = 0; i < EPW; i++)
            if (i < ne) atomicAdd(&g_cnt[d[i]], 1);
    }
    #pragma unroll
    for (int i = 0; i < EPW; i++)
        if (i < ne)
            atomicAdd((float4*)(g_agg + (size_t)d[i] * DD + lane * 4), v[i]);
}

// ---------------------------------------------------------------------------
__global__ void scatter2_kernel(const int* __restrict__ src,
                                const int* __restrict__ dst, int e) {
    int i = blockIdx.x * blockDim.x + threadIdx.x;
    if (i >= e) return;
    int s = __ldg(src + i);
    int d = __ldg(dst + i);
    atomicAdd(&g_aq0[d], g_q0[s]);
    atomicAdd(&g_aq1[d], g_q1[s]);
}

// ---------------------------------------------------------------------------
// u/v projections, one warp per output row.
// ---------------------------------------------------------------------------
__global__ void uv_kernel(const float* __restrict__ W2l,
                          const float* __restrict__ W2r,
                          const float* __restrict__ b2,
                          const float* __restrict__ Wlin,
                          const float* __restrict__ blin) {
    int w    = (blockIdx.x * blockDim.x + threadIdx.x) >> 5;
    int lane = threadIdx.x & 31;
    if (w >= DD) return;
    const float* rl = W2l + (size_t)w * DD;
    const float* rr = W2r + (size_t)w * DD;
    float u0 = 0.f, u1 = 0.f, v0 = 0.f, v1 = 0.f;
    #pragma unroll
    for (int jj = 0; jj < 4; jj++) {
        int j = lane + 32 * jj;
        float a  = __ldg(rl + j);
        float b  = __ldg(rr + j);
        float w0 = __ldg(Wlin + j);
        float w1 = __ldg(Wlin + DD + j);
        u0 = fmaf(a, w0, u0);
        u1 = fmaf(a, w1, u1);
        v0 = fmaf(b, w0, v0);
        v1 = fmaf(b, w1, v1);
    }
    #pragma unroll
    for (int o = 16; o > 0; o >>= 1) {
        u0 += __shfl_down_sync(0xFFFFFFFFu, u0, o);
        u1 += __shfl_down_sync(0xFFFFFFFFu, u1, o);
        v0 += __shfl_down_sync(0xFFFFFFFFu, v0, o);
        v1 += __shfl_down_sync(0xFFFFFFFFu, v1, o);
    }
    if (lane == 0) {
        g_u0[w] = u0; g_u1[w] = u1; g_v0[w] = v0; g_v1[w] = v1;
    }
    if (w == 0) {
        float c = 0.f;
        #pragma unroll
        for (int jj = 0; jj < 4; jj++) {
            int j = lane + 32 * jj;
            c = fmaf(__ldg(b2 + j), __ldg(Wlin + j) + __ldg(Wlin + DD + j), c);
        }
        #pragma unroll
        for (int o = 16; o > 0; o >>= 1)
            c += __shfl_down_sync(0xFFFFFFFFu, c, o);
        if (lane == 0) g_c = c + __ldg(blin);
    }
}

// ---------------------------------------------------------------------------
// bf16-split tensor-core GEMM (mma.sync m16n8k16) fused with projection,
// software-pipelined: A-staging loads for the next half/tile are issued
// before each MMA phase so DRAM latency hides behind tensor work.
// ---------------------------------------------------------------------------
#define GT 512
#define SM_WHI 0                   // [256][136] bf16 = 69632
#define SM_WLO 69632
#define SM_AHI 139264              // [128][136] bf16 = 34816
#define SM_ALO 174080
#define SM_PART 208896             // float[4][128][4] = 8192
#define SM_BIAS 217088             // 512
#define SM_PROJ 217600             // 4 x 512
#define SMEM_TOTAL 219648

__device__ __forceinline__ uint32_t smem_u32(const void* p) {
    uint32_t a;
    asm("{ .reg .u64 t; cvta.to.shared.u64 t, %1; cvt.u32.u64 %0, t; }"
        : "=r"(a) : "l"(p));
    return a;
}

__device__ __forceinline__ void split2(float a, float b,
                                       uint32_t& hi2, uint32_t& lo2) {
    uint32_t ia = __float_as_uint(a) & 0xFFFF0000u;
    uint32_t ib = __float_as_uint(b) & 0xFFFF0000u;
    hi2 = (ia >> 16) | ib;
    float la = a - __uint_as_float(ia);
    float lb = b - __uint_as_float(ib);
    asm("cvt.rn.bf16x2.f32 %0, %1, %2;" : "=r"(lo2) : "f"(lb), "f"(la));
}

__device__ __forceinline__ void ldsm_x4(uint32_t* r, uint32_t addr) {
    asm volatile("ldmatrix.sync.aligned.m8n8.x4.shared.b16 {%0,%1,%2,%3}, [%4];"
        : "=r"(r[0]), "=r"(r[1]), "=r"(r[2]), "=r"(r[3]) : "r"(addr));
}

__device__ __forceinline__ void ldsm_x2t(uint32_t* r, uint32_t addr) {
    asm volatile("ldmatrix.sync.aligned.m8n8.x2.trans.shared.b16 {%0,%1}, [%2];"
        : "=r"(r[0]), "=r"(r[1]) : "r"(addr));
}

__device__ __forceinline__ void mma_bf16(float* d, const uint32_t* a,
                                         const uint32_t* b) {
    asm volatile("mma.sync.aligned.m16n8k16.row.col.f32.bf16.bf16.f32 "
        "{%0,%1,%2,%3}, {%4,%5,%6,%7}, {%8,%9}, {%0,%1,%2,%3};"
        : "+f"(d[0]), "+f"(d[1]), "+f"(d[2]), "+f"(d[3])
        : "r"(a[0]), "r"(a[1]), "r"(a[2]), "r"(a[3]), "r"(b[0]), "r"(b[1]));
}

__global__ __launch_bounds__(GT, 1)
void sage_gemm_mma(const float* __restrict__ agg,
                   const float* __restrict__ xin,
                   const float* __restrict__ Wl,
                   const float* __restrict__ bias,
                   const float* __restrict__ Wr,
                   int n) {
    extern __shared__ char smem[];
    const uint32_t sb = smem_u32(smem);
    const int tid  = threadIdx.x;
    const int lane = tid & 31;
    const int wid  = tid >> 5;
    const int mi   = wid >> 2;
    const int ni   = wid & 3;
    const int c4   = tid & 31;   // staging column group
    const int rw   = tid >> 5;   // staging base row

    // Stage W_cat = [W1l ; W1r] as bf16 hi/lo.
    for (int i = tid; i < 256 * 32; i += GT) {
        int row = i >> 5, cc = i & 31;
        const float* wsrc = (row < 128) ? (Wl + (size_t)row * 128)
                                        : (Wr + (size_t)(row - 128) * 128);
        float4 v = ((const float4*)wsrc)[cc];
        uint32_t h01, l01, h23, l23;
        split2(v.x, v.y, h01, l01);
        split2(v.z, v.w, h23, l23);
        *(uint2*)(smem + SM_WHI + row * 272 + cc * 8) = make_uint2(h01, h23);
        *(uint2*)(smem + SM_WLO + row * 272 + cc * 8) = make_uint2(l01, l23);
    }
    if (tid < DD) {
        ((float*)(smem + SM_BIAS))[tid]        = bias[tid];
        ((float*)(smem + SM_PROJ))[tid]        = g_u0[tid];
        ((float*)(smem + SM_PROJ + 512))[tid]  = g_u1[tid];
        ((float*)(smem + SM_PROJ + 1024))[tid] = g_v0[tid];
        ((float*)(smem + SM_PROJ + 1536))[tid] = g_v1[tid];
    }
    __syncthreads();

    const int ntiles = (n + 127) >> 7;

    float4 vb[8];
    // Prologue: batch-load first tile's agg half (scaled by inv at load).
    if (blockIdx.x < ntiles) {
        const int base = blockIdx.x << 7;
        #pragma unroll
        for (int j = 0; j < 8; j++) {
            int grc = min(base + rw + 16 * j, n - 1);
            float4 a = ((const float4*)(agg + (size_t)grc * DD))[c4];
            float iv = g_inv[grc];
            a.x *= iv; a.y *= iv; a.z *= iv; a.w *= iv;
            vb[j] = a;
        }
    }

    for (int t = blockIdx.x; t < ntiles; t += gridDim.x) {
        const int base = t << 7;

        float D[2][4][4];
        #pragma unroll
        for (int mt = 0; mt < 2; mt++)
            #pragma unroll
            for (int nt = 0; nt < 4; nt++)
                #pragma unroll
                for (int j = 0; j < 4; j++) D[mt][nt][j] = 0.f;

        // ---- store h0 (agg batch already in vb) ----
        #pragma unroll
        for (int j = 0; j < 8; j++) {
            int row = rw + 16 * j;
            uint32_t h01, l01, h23, l23;
            split2(vb[j].x, vb[j].y, h01, l01);
            split2(vb[j].z, vb[j].w, h23, l23);
            *(uint2*)(smem + SM_AHI + row * 272 + c4 * 8) = make_uint2(h01, h23);
            *(uint2*)(smem + SM_ALO + row * 272 + c4 * 8) = make_uint2(l01, l23);
        }
        __syncthreads();

        // ---- prefetch h1 (emb) while mma(h0) runs ----
        #pragma unroll
        for (int j = 0; j < 8; j++) {
            int grc = min(base + rw + 16 * j, n - 1);
            vb[j] = ((const float4*)(xin + (size_t)grc * DD))[c4];
        }

        // ---- mma over h0 ----
        #pragma unroll
        for (int ks = 0; ks < 8; ks++) {
            const int kb = ks * 16;
            uint32_t bh[4][2], bl[4][2];
            uint32_t bko = (kb + (lane & 15)) * 272;
            #pragma unroll
            for (int nt = 0; nt < 4; nt++) {
                uint32_t cb2 = (ni * 32 + nt * 8) * 2;
                ldsm_x2t(bh[nt], sb + SM_WHI + bko + cb2);
                ldsm_x2t(bl[nt], sb + SM_WLO + bko + cb2);
            }
            uint32_t ah[2][4], al[2][4];
            uint32_t arow = (lane & 7) + ((lane >> 3) & 1) * 8;
            uint32_t akc  = kb + (lane >> 4) * 8;
            #pragma unroll
            for (int mt = 0; mt < 2; mt++) {
                uint32_t off = (mi * 32 + mt * 16 + arow) * 272 + akc * 2;
                ldsm_x4(ah[mt], sb + SM_AHI + off);
                ldsm_x4(al[mt], sb + SM_ALO + off);
            }
            #pragma unroll
            for (int mt = 0; mt < 2; mt++)
                #pragma unroll
                for (int nt = 0; nt < 4; nt++) {
                    mma_bf16(D[mt][nt], ah[mt], bh[nt]);
                    mma_bf16(D[mt][nt], ah[mt], bl[nt]);
                    mma_bf16(D[mt][nt], al[mt], bh[nt]);
                }
        }
        __syncthreads();   // all warps done reading A(h0)

        // ---- store h1 ----
        #pragma unroll
        for (int j = 0; j < 8; j++) {
            int row = rw + 16 * j;
            uint32_t h01, l01, h23, l23;
            split2(vb[j].x, vb[j].y, h01, l01);
            split2(vb[j].z, vb[j].w, h23, l23);
            *(uint2*)(smem + SM_AHI + row * 272 + c4 * 8) = make_uint2(h01, h23);
            *(uint2*)(smem + SM_ALO + row * 272 + c4 * 8) = make_uint2(l01, l23);
        }
        __syncthreads();

        // ---- prefetch next tile h0 (agg) while mma(h1) runs ----
        int tn = t + gridDim.x;
        if (tn < ntiles) {
            const int nb = tn << 7;
            #pragma unroll
            for (int j = 0; j < 8; j++) {
                int grc = min(nb + rw + 16 * j, n - 1);
                float4 a = ((const float4*)(agg + (size_t)grc * DD))[c4];
                float iv = g_inv[grc];
                a.x *= iv; a.y *= iv; a.z *= iv; a.w *= iv;
                vb[j] = a;
            }
        }

        // ---- mma over h1 ----
        #pragma unroll
        for (int ks = 0; ks < 8; ks++) {
            const int kb = ks * 16;
            uint32_t bh[4][2], bl[4][2];
            uint32_t bko = (128 + kb + (lane & 15)) * 272;
            #pragma unroll
            for (int nt = 0; nt < 4; nt++) {
                uint32_t cb2 = (ni * 32 + nt * 8) * 2;
                ldsm_x2t(bh[nt], sb + SM_WHI + bko + cb2);
                ldsm_x2t(bl[nt], sb + SM_WLO + bko + cb2);
            }
            uint32_t ah[2][4], al[2][4];
            uint32_t arow = (lane & 7) + ((lane >> 3) & 1) * 8;
            uint32_t akc  = kb + (lane >> 4) * 8;
            #pragma unroll
            for (int mt = 0; mt < 2; mt++) {
                uint32_t off = (mi * 32 + mt * 16 + arow) * 272 + akc * 2;
                ldsm_x4(ah[mt], sb + SM_AHI + off);
                ldsm_x4(al[mt], sb + SM_ALO + off);
            }
            #pragma unroll
            for (int mt = 0; mt < 2; mt++)
                #pragma unroll
                for (int nt = 0; nt < 4; nt++) {
                    mma_bf16(D[mt][nt], ah[mt], bh[nt]);
                    mma_bf16(D[mt][nt], ah[mt], bl[nt]);
                    mma_bf16(D[mt][nt], al[mt], bh[nt]);
                }
        }

        // ---- epilogue: relu+bias, project, reduce ----
        const float* bs  = (const float*)(smem + SM_BIAS);
        const float* pu0 = (const float*)(smem + SM_PROJ);
        const float* pu1 = (const float*)(smem + SM_PROJ + 512);
        const float* pv0 = (const float*)(smem + SM_PROJ + 1024);
        const float* pv1 = (const float*)(smem + SM_PROJ + 1536);
        float* part = (float*)(smem + SM_PART);
        const int g = lane >> 2, c = lane & 3;

        #pragma unroll
        for (int mt = 0; mt < 2; mt++) {
            float pl[4] = {0.f, 0.f, 0.f, 0.f};
            float ph[4] = {0.f, 0.f, 0.f, 0.f};
            #pragma unroll
            for (int nt = 0; nt < 4; nt++) {
                int col = ni * 32 + nt * 8 + 2 * c;
                float b0 = bs[col], b1 = bs[col + 1];
                float s00 = fmaxf(D[mt][nt][0] + b0, 0.f);
                float s01 = fmaxf(D[mt][nt][1] + b1, 0.f);
                float s10 = fmaxf(D[mt][nt][2] + b0, 0.f);
                float s11 = fmaxf(D[mt][nt][3] + b1, 0.f);
                float a0, a1;
                a0 = pu0[col]; a1 = pu0[col + 1];
                pl[0] += s00 * a0 + s01 * a1;  ph[0] += s10 * a0 + s11 * a1;
                a0 = pu1[col]; a1 = pu1[col + 1];
                pl[1] += s00 * a0 + s01 * a1;  ph[1] += s10 * a0 + s11 * a1;
                a0 = pv0[col]; a1 = pv0[col + 1];
                pl[2] += s00 * a0 + s01 * a1;  ph[2] += s10 * a0 + s11 * a1;
                a0 = pv1[col]; a1 = pv1[col + 1];
                pl[3] += s00 * a0 + s01 * a1;  ph[3] += s10 * a0 + s11 * a1;
            }
            #pragma unroll
            for (int o = 1; o <= 2; o <<= 1) {
                #pragma unroll
                for (int j = 0; j < 4; j++) {
                    pl[j] += __shfl_xor_sync(0xFFFFFFFFu, pl[j], o);
                    ph[j] += __shfl_xor_sync(0xFFFFFFFFu, ph[j], o);
                }
            }
            if (c == 0) {
                int rl = mi * 32 + mt * 16 + g;
                int rh = rl + 8;
                #pragma unroll
                for (int j = 0; j < 4; j++) {
                    part[j * 512 + rl * 4 + ni] = pl[j];
                    part[j * 512 + rh * 4 + ni] = ph[j];
                }
            }
        }
        __syncthreads();
        if (tid < 128) {
            int gr = base + tid;
            if (gr < n) {
                float s[4];
                #pragma unroll
                for (int j = 0; j < 4; j++) {
                    const float* p = part + j * 512 + tid * 4;
                    s[j] = p[0] + p[1] + p[2] + p[3];
                }
                g_q0 [gr] = s[0];
                g_q1 [gr] = s[1];
                g_xv0[gr] = s[2];
                g_xv1[gr] = s[3];
            }
        }
        // next tile's h0-store sync orders part/A reuse
    }
}

// ---------------------------------------------------------------------------
__global__ void fold_kernel(int n) {
    int v = blockIdx.x * blockDim.x + threadIdx.x;
    if (v >= n) return;
    float inv = g_inv[v];
    g_r0[v] = fmaf(inv, g_aq0[v], g_xv0[v]);
    g_r1[v] = fmaf(inv, g_aq1[v], g_xv1[v]);
}

// ---------------------------------------------------------------------------
__global__ void predict_kernel(const int* __restrict__ s,
                               const int* __restrict__ d,
                               float* __restrict__ out, int L) {
    int l = blockIdx.x * blockDim.x + threadIdx.x;
    if (l >= L) return;
    out[l] = g_r0[__ldg(s + l)] + g_r1[__ldg(d + l)] + g_c;
}

// ---------------------------------------------------------------------------
extern "C" void kernel_launch(void* const* d_in, const int* in_sizes, int n_in,
                              void* d_out, int out_size) {
    const int*   ei   = (const int*)d_in[0];
    const int*   eli  = (const int*)d_in[1];
    const float* emb  = (const float*)d_in[2];
    const float* W1l  = (const float*)d_in[3];
    const float* b1   = (const float*)d_in[4];
    const float* W1r  = (const float*)d_in[5];
    const float* W2l  = (const float*)d_in[6];
    const float* b2   = (const float*)d_in[7];
    const float* W2r  = (const float*)d_in[8];
    const float* Wlin = (const float*)d_in[9];
    const float* blin = (const float*)d_in[10];
    float*       out  = (float*)d_out;

    const int E = in_sizes[0] / 2;
    const int L = in_sizes[1] / 2;
    const int N = in_sizes[2] / DD;

    const int* src = ei;
    const int* dst = ei + E;
    const int* ls  = eli;
    const int* ld  = eli + L;

    void* p_agg = nullptr; cudaGetSymbolAddress(&p_agg, g_agg);
    void* p_cnt = nullptr; cudaGetSymbolAddress(&p_cnt, g_cnt);
    float* agg = (float*)p_agg;

    cudaFuncSetAttribute(sage_gemm_mma,
                         cudaFuncAttributeMaxDynamicSharedMemorySize,
                         SMEM_TOTAL);

    const int nwarps = (E + EPW - 1) / EPW;
    const int scatter_blocks = ((size_t)nwarps * 32 + 255) / 256;

    // Setup
    cudaMemsetAsync(p_cnt, 0, sizeof(int) * (size_t)N);
    cudaMemsetAsync(p_agg, 0, sizeof(float) * (size_t)N * DD);
    uv_kernel<<<16, 256>>>(W2l, W2r, b2, Wlin, blin);

    // Layer 1 aggregation (with fused degree count) + tensor-core GEMM
    scatter_kernel<<<scatter_blocks, 256>>>(emb, src, dst, E);
    inv_kernel<<<(N + 255) / 256, 256>>>(N);
    sage_gemm_mma<<<148, GT, SMEM_TOTAL>>>(agg, emb, W1l, b1, W1r, N);

    // Layer 2: scalar scatter + fold + predict
    scatter2_kernel<<<(E + 255) / 256, 256>>>(src, dst, E);
    fold_kernel<<<(N + 255) / 256, 256>>>(N);
    predict_kernel<<<(L + 255) / 256, 256>>>(ls, ld, out, L);
}